// round 10
// baseline (speedup 1.0000x reference)
#include <cuda_runtime.h>

// LearnableWaveletTransform: depthwise 1D cross-correlation, 2 shared 96-tap
// filters over x[64,128,4096] fp32, pad=48 -> out (l,h) each [64,128,4097].
//
// R8b (re-run of R8; previous round was an infra container failure):
// R5 base (float smem window, skew l+(l>>4), FFMA2 filter-pair packing,
// staged coalesced stores) plus:
//  - strength-reduced skew addressing: phys(s0+c) = tid*17 + c + (c>>4);
//    base pointer bumps +17 floats per outer iter, inner offsets immediate.
//  - weight double-buffer: prefetch w[k+1] before FMAs of w[k] (36-cyc slack
//    vs 29-cyc LDS latency -> no dependent stall).
//  - x refill load issued before the FMA block.
// NOTE: window stays FLOAT (R7's ull window made lane stride 34 banks ->
// 2-way conflicts on every LDS.64; that regression is reverted).

#define KW      96
#define PADW    48
#define TLEN    4096
#define TOUT    4097
#define NROWS   8192            // 64 * 128
#define NTHREADS 256
#define RPT     16
#define TILE    (NTHREADS * RPT)        // 4096
#define WINLEN  (TILE + KW)             // 4192
#define SKEWLEN (WINLEN + (WINLEN >> 4))  // 4454 floats
#define HALFOFF ((long long)NROWS * (long long)TOUT)  // 33,562,624

typedef unsigned long long ull;

__device__ __forceinline__ ull ffma2(ull a, ull b, ull c) {
    ull d;
    asm("fma.rn.f32x2 %0, %1, %2, %3;" : "=l"(d) : "l"(a), "l"(b), "l"(c));
    return d;
}
__device__ __forceinline__ ull pack2(float lo, float hi) {
    ull r;
    asm("mov.b64 %0, {%1, %2};" : "=l"(r) : "f"(lo), "f"(hi));
    return r;
}
__device__ __forceinline__ void unpack2(ull v, float& lo, float& hi) {
    asm("mov.b64 {%0, %1}, %2;" : "=f"(lo), "=f"(hi) : "l"(v));
}

__global__ void __launch_bounds__(NTHREADS, 3)
wavelet_f32x2_r8(const float* __restrict__ x,
                 const float* __restrict__ hw,
                 const float* __restrict__ lw,
                 float* __restrict__ out)
{
    __shared__ float sxs[SKEWLEN];
    __shared__ ull wp[KW + 1];          // +1 pad for harmless prefetch overrun

    const int row = blockIdx.x;
    const int tid = threadIdx.x;
    const long long xbase = (long long)row * TLEN;

    // Skewed cooperative window fill: sxs[i + (i>>4)] = x[row, i - PADW] (0-pad)
    for (int i = tid; i < WINLEN; i += NTHREADS) {
        int g = i - PADW;
        sxs[i + (i >> 4)] = (g >= 0 && g < TLEN) ? x[xbase + g] : 0.0f;
    }
    if (tid < KW) wp[tid] = pack2(lw[tid], hw[tid]);   // lane.lo=l, lane.hi=h
    if (tid == KW) wp[KW] = 0ULL;
    __syncthreads();

    const int s0 = tid * RPT;                    // multiple of 16
    const float* pbase = sxs + tid * 17;         // phys(s0 + j) = pbase[j], j<16

    // Sliding register window of duplicated-pair x values (16 deep)
    ull xd[RPT];
    #pragma unroll
    for (int j = 0; j < RPT; ++j) {
        float v = pbase[j];
        xd[j] = pack2(v, v);
    }

    ull acc[RPT];
    #pragma unroll
    for (int j = 0; j < RPT; ++j) acc[j] = 0ULL;

    // phys(s0 + 16 + kk + ki) = tid*17 + 17*(1 + kk/16) + ki  (immediate ki)
    ull wcur = wp[0];
    #pragma unroll 1
    for (int kk = 0; kk < KW; kk += RPT) {
        const float* px = pbase + 17 * (kk / RPT + 1);
        const ull*   pw = wp + kk;
        #pragma unroll
        for (int ki = 0; ki < RPT; ++ki) {
            float xnew = px[ki];          // LDS early: consumed 16 FMAs later
            ull   wnxt = pw[ki + 1];      // prefetch next weight (36-cyc slack)
            #pragma unroll
            for (int j = 0; j < RPT; ++j)
                acc[j] = ffma2(xd[j], wcur, acc[j]);
            #pragma unroll
            for (int j = 0; j < RPT - 1; ++j) xd[j] = xd[j + 1];
            xd[RPT - 1] = pack2(xnew, xnew);
            wcur = wnxt;
        }
    }

    float lacc[RPT], hacc[RPT];
    #pragma unroll
    for (int j = 0; j < RPT; ++j) unpack2(acc[j], lacc[j], hacc[j]);

    // Tail output t = 4096 (read sxs before staging overwrites it)
    float tl = 0.0f, th = 0.0f;
    if (tid == NTHREADS - 1) {
        ull e = 0ULL;
        #pragma unroll 16
        for (int k = 0; k < KW; ++k) {
            int i = TILE + k;
            float v = sxs[i + (i >> 4)];
            e = ffma2(pack2(v, v), wp[k], e);
        }
        unpack2(e, tl, th);
    }

    const long long obase = (long long)row * TOUT;

    // Stage l through smem -> coalesced STG
    __syncthreads();
    #pragma unroll
    for (int j = 0; j < RPT; ++j)
        sxs[tid * 17 + j] = lacc[j];               // phys(s0+j), conflict-free
    __syncthreads();
    #pragma unroll
    for (int j = 0; j < RPT; ++j) {
        int t = tid + j * NTHREADS;                // lane-consecutive
        out[obase + t] = sxs[t + (t >> 4)];
    }

    // Stage h
    __syncthreads();
    #pragma unroll
    for (int j = 0; j < RPT; ++j)
        sxs[tid * 17 + j] = hacc[j];
    __syncthreads();
    #pragma unroll
    for (int j = 0; j < RPT; ++j) {
        int t = tid + j * NTHREADS;
        out[HALFOFF + obase + t] = sxs[t + (t >> 4)];
    }

    if (tid == NTHREADS - 1) {
        out[obase + TLEN]           = tl;
        out[HALFOFF + obase + TLEN] = th;
    }
}

extern "C" void kernel_launch(void* const* d_in, const int* in_sizes, int n_in,
                              void* d_out, int out_size) {
    // metadata order: x, h_w, l_w ; output: (l_outs, h_outs) concatenated
    const float* x  = (const float*)d_in[0];
    const float* hw = (const float*)d_in[1];
    const float* lw = (const float*)d_in[2];
    float* out = (float*)d_out;

    dim3 grid(NROWS);
    dim3 block(NTHREADS);
    wavelet_f32x2_r8<<<grid, block>>>(x, hw, lw, out);
}

// round 12
// speedup vs baseline: 1.7525x; 1.7525x over previous
#include <cuda_runtime.h>

// LearnableWaveletTransform: depthwise 1D cross-correlation, 2 shared 96-tap
// filters over x[64,128,4096] fp32, pad=48 -> out (l,h) each [64,128,4097].
//
// R10: occupancy push. RPT=8 (was 16) -> ~48 regs -> 5 blocks/SM = 40 warps
// (10/SMSP, was 6/SMSP). Skew changed to phys=i+(i>>3): lane bank = 9*lane
// mod 32, gcd(9,32)=1 -> conflict-free for the stride-8 window access.
// Keeps FFMA2 filter-pair packing + staged coalesced stores (proven in R5).
// TILE=2048, grid (2, 8192); tail t=4096 handled by tile 1.

#define KW      96
#define PADW    48
#define TLEN    4096
#define TOUT    4097
#define NROWS   8192            // 64 * 128
#define NTHREADS 256
#define RPT     8
#define TILE    (NTHREADS * RPT)        // 2048
#define WINLEN  (TILE + KW)             // 2144
#define SKEWLEN (WINLEN + (WINLEN >> 3))  // 2412 floats (~9.6 KB)
#define HALFOFF ((long long)NROWS * (long long)TOUT)  // 33,562,624

typedef unsigned long long ull;

__device__ __forceinline__ ull ffma2(ull a, ull b, ull c) {
    ull d;
    asm("fma.rn.f32x2 %0, %1, %2, %3;" : "=l"(d) : "l"(a), "l"(b), "l"(c));
    return d;
}
__device__ __forceinline__ ull pack2(float lo, float hi) {
    ull r;
    asm("mov.b64 %0, {%1, %2};" : "=l"(r) : "f"(lo), "f"(hi));
    return r;
}
__device__ __forceinline__ void unpack2(ull v, float& lo, float& hi) {
    asm("mov.b64 {%0, %1}, %2;" : "=f"(lo), "=f"(hi) : "l"(v));
}

__global__ void __launch_bounds__(NTHREADS, 5)
wavelet_f32x2_r10(const float* __restrict__ x,
                  const float* __restrict__ hw,
                  const float* __restrict__ lw,
                  float* __restrict__ out)
{
    __shared__ float sxs[SKEWLEN];
    __shared__ ull wp[KW + 1];          // +1 pad: harmless prefetch overrun

    const int row  = blockIdx.y;
    const int tile = blockIdx.x;
    const int tid  = threadIdx.x;
    const long long xbase = (long long)row * TLEN;
    const int t_base = tile * TILE;
    const int g0 = t_base - PADW;

    // Skewed window fill: sxs[i + (i>>3)] = x[row, g0 + i] (0-pad at edges)
    for (int i = tid; i < WINLEN; i += NTHREADS) {
        int g = g0 + i;
        sxs[i + (i >> 3)] = (g >= 0 && g < TLEN) ? x[xbase + g] : 0.0f;
    }
    if (tid < KW) wp[tid] = pack2(lw[tid], hw[tid]);   // lane.lo=l, lane.hi=h
    if (tid == KW) wp[KW] = 0ULL;
    __syncthreads();

    // s0 = tid*8 is 8-aligned -> phys(s0 + 8m + c) = 9*tid + 9m + c (c<8)
    const float* pbase = sxs + tid * 9;

    ull xd[RPT];
    #pragma unroll
    for (int j = 0; j < RPT; ++j) {
        float v = pbase[j];
        xd[j] = pack2(v, v);
    }

    ull acc[RPT];
    #pragma unroll
    for (int j = 0; j < RPT; ++j) acc[j] = 0ULL;

    ull wcur = wp[0];
    #pragma unroll 1
    for (int kk = 0; kk < KW; kk += RPT) {      // 12 outer iterations
        const float* px = pbase + 9 * (kk / RPT + 1);
        const ull*   pw = wp + kk;
        #pragma unroll
        for (int ki = 0; ki < RPT; ++ki) {
            float xnew = px[ki];                // conflict-free (9*lane banks)
            ull   wnxt = pw[ki + 1];
            #pragma unroll
            for (int j = 0; j < RPT; ++j)
                acc[j] = ffma2(xd[j], wcur, acc[j]);
            #pragma unroll
            for (int j = 0; j < RPT - 1; ++j) xd[j] = xd[j + 1];
            xd[RPT - 1] = pack2(xnew, xnew);
            wcur = wnxt;
        }
    }

    float lacc[RPT], hacc[RPT];
    #pragma unroll
    for (int j = 0; j < RPT; ++j) unpack2(acc[j], lacc[j], hacc[j]);

    // Tail output t = 4096: tile 1 window idx 2048..2143 (read before staging)
    float tl = 0.0f, th = 0.0f;
    if (tile == 1 && tid == NTHREADS - 1) {
        ull e = 0ULL;
        #pragma unroll 8
        for (int k = 0; k < KW; ++k) {
            int i = TILE + k;
            float v = sxs[i + (i >> 3)];
            e = ffma2(pack2(v, v), wp[k], e);
        }
        unpack2(e, tl, th);
    }

    const long long obase = (long long)row * TOUT + t_base;

    // Stage l -> coalesced STG
    __syncthreads();
    #pragma unroll
    for (int j = 0; j < RPT; ++j)
        sxs[tid * 9 + j] = lacc[j];             // phys(s0+j), conflict-free
    __syncthreads();
    #pragma unroll
    for (int j = 0; j < RPT; ++j) {
        int t = tid + j * NTHREADS;             // lane-consecutive
        out[obase + t] = sxs[t + (t >> 3)];
    }

    // Stage h
    __syncthreads();
    #pragma unroll
    for (int j = 0; j < RPT; ++j)
        sxs[tid * 9 + j] = hacc[j];
    __syncthreads();
    #pragma unroll
    for (int j = 0; j < RPT; ++j) {
        int t = tid + j * NTHREADS;
        out[HALFOFF + obase + t] = sxs[t + (t >> 3)];
    }

    if (tile == 1 && tid == NTHREADS - 1) {
        long long ob = (long long)row * TOUT;
        out[ob + TLEN]           = tl;
        out[HALFOFF + ob + TLEN] = th;
    }
}

extern "C" void kernel_launch(void* const* d_in, const int* in_sizes, int n_in,
                              void* d_out, int out_size) {
    // metadata order: x, h_w, l_w ; output: (l_outs, h_outs) concatenated
    const float* x  = (const float*)d_in[0];
    const float* hw = (const float*)d_in[1];
    const float* lw = (const float*)d_in[2];
    float* out = (float*)d_out;

    dim3 grid(2, NROWS);
    dim3 block(NTHREADS);
    wavelet_f32x2_r10<<<grid, block>>>(x, hw, lw, out);
}